// round 2
// baseline (speedup 1.0000x reference)
#include <cuda_runtime.h>
#include <cstdint>
#include <cstddef>

#define N_NODES 100000
#define N_EDGES 1600000

// ---------------- scratch (device globals; no runtime allocation) ----------------
// g_NP layout per node (256 floats):
//   [0:64)    x_n @ W_f[0:64]   + b_f   (src part, f)
//   [64:128)  x_n @ W_s[0:64]   + b_s   (src part, s)
//   [128:192) x_n @ W_f[64:128]         (tgt part, f)
//   [192:256) x_n @ W_s[64:128]         (tgt part, s)
__device__ __align__(16) float g_NP[(size_t)N_NODES * 256];
__device__ __align__(16) float g_msg[(size_t)N_NODES * 64];
__device__ double g_stats[128];   // [0:64) sum, [64:128) sumsq
__device__ float g_scale[64];
__device__ float g_shift[64];
__device__ int   g_is64;

// ---------------- helpers ----------------
union F2U { unsigned long long u; float2 f2; float f[2]; };

__device__ __forceinline__ unsigned long long ffma2(unsigned long long a,
                                                    unsigned long long b,
                                                    unsigned long long c) {
    unsigned long long d;
    asm("fma.rn.f32x2 %0, %1, %2, %3;" : "=l"(d) : "l"(a), "l"(b), "l"(c));
    return d;
}
__device__ __forceinline__ unsigned long long pk2(float x, float y) {
    F2U u; u.f2 = make_float2(x, y); return u.u;
}
__device__ __forceinline__ void red4(float* p, float a, float b, float c, float d) {
    asm volatile("red.global.add.v4.f32 [%0], {%1,%2,%3,%4};"
                 :: "l"(p), "f"(a), "f"(b), "f"(c), "f"(d) : "memory");
}
__device__ __forceinline__ float sigmoidf_(float x) {
    return __fdividef(1.0f, 1.0f + __expf(-x));
}
__device__ __forceinline__ float softplusf_(float x) {
    return (x > 15.0f) ? x : __logf(1.0f + __expf(x));
}

// ---------------- kernel 0: edge_index dtype detection ----------------
// If data is int64 (values < 2^31), hi 32-bit word of every slot is 0.
// If data is int32, the "hi word" is the next random index (almost surely nonzero
// somewhere within 1024 slots).
__global__ void detect_dtype(const unsigned int* __restrict__ ei32) {
    __shared__ unsigned int acc;
    int tid = threadIdx.x;
    if (tid == 0) acc = 0u;
    __syncthreads();
    unsigned int v = 0u;
    for (int i = tid; i < 1024; i += 256) v |= ei32[2 * i + 1];
    atomicOr(&acc, v);
    __syncthreads();
    if (tid == 0) g_is64 = (acc == 0u) ? 1 : 0;
}

// ---------------- kernel 1: per-node projection GEMM ----------------
// NP[64 nodes x 256 cols] tile per block. K=64 in two chunks of 32.
__global__ void __launch_bounds__(256, 2) node_gemm(
    const float* __restrict__ node, const float* __restrict__ Wf,
    const float* __restrict__ bf, const float* __restrict__ Ws,
    const float* __restrict__ bs)
{
    __shared__ float Ast[32][68];    // A transposed: [k][node]
    __shared__ float Bs[32][256];

    const int tid = threadIdx.x;
    const int cx = tid & 31;         // col group: cols 8*cx .. 8*cx+7 of 256
    const int ey = tid >> 5;         // node group: nodes 8*ey .. 8*ey+7 of 64
    const int nb = blockIdx.x * 64;

    F2U acc[8][4];
#pragma unroll
    for (int i = 0; i < 8; ++i)
#pragma unroll
        for (int j = 0; j < 4; ++j) acc[i][j].u = 0ULL;

    for (int kt = 0; kt < 2; ++kt) {
        // A chunk: node_attrs[nb..nb+63][kt*32 .. +31], transposed into Ast
#pragma unroll
        for (int it = 0; it < 8; ++it) {
            int idx = it * 256 + tid;
            int n = idx >> 5, k = idx & 31;
            float v = 0.0f;
            if (nb + n < N_NODES) v = node[(size_t)(nb + n) * 64 + kt * 32 + k];
            Ast[k][n] = v;
        }
        // B chunk: 32 x 256 built from W_f / W_s rows
#pragma unroll
        for (int it = 0; it < 32; ++it) {
            int idx = it * 256 + tid;
            int k = idx >> 8, c = idx & 255;
            int kk = kt * 32 + k;
            float v;
            if (c < 64)       v = Wf[kk * 64 + c];
            else if (c < 128) v = Ws[kk * 64 + (c - 64)];
            else if (c < 192) v = Wf[(64 + kk) * 64 + (c - 128)];
            else              v = Ws[(64 + kk) * 64 + (c - 192)];
            Bs[k][c] = v;
        }
        __syncthreads();
#pragma unroll 8
        for (int k = 0; k < 32; ++k) {
            float4 a0 = *(const float4*)&Ast[k][ey * 8];
            float4 a1 = *(const float4*)&Ast[k][ey * 8 + 4];
            float4 b0 = *(const float4*)&Bs[k][cx * 8];
            float4 b1 = *(const float4*)&Bs[k][cx * 8 + 4];
            unsigned long long bp[4] = { pk2(b0.x, b0.y), pk2(b0.z, b0.w),
                                         pk2(b1.x, b1.y), pk2(b1.z, b1.w) };
            float av[8] = { a0.x, a0.y, a0.z, a0.w, a1.x, a1.y, a1.z, a1.w };
#pragma unroll
            for (int i = 0; i < 8; ++i) {
                unsigned long long aa = pk2(av[i], av[i]);
#pragma unroll
                for (int j = 0; j < 4; ++j) acc[i][j].u = ffma2(aa, bp[j], acc[i][j].u);
            }
        }
        __syncthreads();
    }

    float bias[8];
#pragma unroll
    for (int j = 0; j < 8; ++j) {
        int c = cx * 8 + j;
        bias[j] = (c < 64) ? bf[c] : ((c < 128) ? bs[c - 64] : 0.0f);
    }
#pragma unroll
    for (int i = 0; i < 8; ++i) {
        int n = nb + ey * 8 + i;
        if (n < N_NODES) {
            float4 o0 = make_float4(acc[i][0].f[0] + bias[0], acc[i][0].f[1] + bias[1],
                                    acc[i][1].f[0] + bias[2], acc[i][1].f[1] + bias[3]);
            float4 o1 = make_float4(acc[i][2].f[0] + bias[4], acc[i][2].f[1] + bias[5],
                                    acc[i][3].f[0] + bias[6], acc[i][3].f[1] + bias[7]);
            float4* dst = (float4*)&g_NP[(size_t)n * 256 + cx * 8];
            dst[0] = o0; dst[1] = o1;
        }
    }
}

// ---------------- kernel 2: fused edge GEMM + gather + activation + scatter ----------------
// Per block: 64 edges. GEMM tile [64 x 128], K=32 (edge_attrs @ [W_f3 | W_s3]).
// Epilogue gathers precomputed node projections, applies sigmoid*softplus,
// scatter-adds to g_msg[src] with vectorized red.
__global__ void __launch_bounds__(256, 2) edge_fused(
    const float* __restrict__ ea, const void* __restrict__ ei,
    const float* __restrict__ Wf, const float* __restrict__ Ws)
{
    __shared__ union {
        struct { float Ast[32][68]; float Bs[32][128]; } m;   // mainloop
        struct { float pre[64][132]; } e;                      // epilogue staging
    } sm;
    __shared__ int s_src[64], s_tgt[64];

    const int tid = threadIdx.x;
    const int eb = blockIdx.x * 64;

    if (tid < 64) {
        int src, tgt;
        if (g_is64) {
            src = (int)((const long long*)ei)[eb + tid];
            tgt = (int)((const long long*)ei)[N_EDGES + eb + tid];
        } else {
            src = ((const int*)ei)[eb + tid];
            tgt = ((const int*)ei)[N_EDGES + eb + tid];
        }
        s_src[tid] = src;
        s_tgt[tid] = tgt;
    }
    // A: edge_attrs tile transposed
#pragma unroll
    for (int it = 0; it < 8; ++it) {
        int idx = it * 256 + tid;
        int e = idx >> 5, k = idx & 31;
        sm.m.Ast[k][e] = ea[(size_t)(eb + e) * 32 + k];
    }
    // B: rows 128..159 of W_f (cols 0..63) and W_s (cols 64..127)
#pragma unroll
    for (int it = 0; it < 16; ++it) {
        int idx = it * 256 + tid;
        int k = idx >> 7, c = idx & 127;
        sm.m.Bs[k][c] = (c < 64) ? Wf[(128 + k) * 64 + c]
                                 : Ws[(128 + k) * 64 + (c - 64)];
    }
    __syncthreads();

    const int cx = tid & 15;   // cols 8*cx .. 8*cx+7 of 128
    const int ey = tid >> 4;   // edges 4*ey .. 4*ey+3
    F2U acc[4][4];
#pragma unroll
    for (int i = 0; i < 4; ++i)
#pragma unroll
        for (int j = 0; j < 4; ++j) acc[i][j].u = 0ULL;

#pragma unroll 8
    for (int k = 0; k < 32; ++k) {
        float4 av = *(const float4*)&sm.m.Ast[k][ey * 4];
        float4 b0 = *(const float4*)&sm.m.Bs[k][cx * 8];
        float4 b1 = *(const float4*)&sm.m.Bs[k][cx * 8 + 4];
        unsigned long long bp[4] = { pk2(b0.x, b0.y), pk2(b0.z, b0.w),
                                     pk2(b1.x, b1.y), pk2(b1.z, b1.w) };
        float a[4] = { av.x, av.y, av.z, av.w };
#pragma unroll
        for (int i = 0; i < 4; ++i) {
            unsigned long long aa = pk2(a[i], a[i]);
#pragma unroll
            for (int j = 0; j < 4; ++j) acc[i][j].u = ffma2(aa, bp[j], acc[i][j].u);
        }
    }
    __syncthreads();   // protect union aliasing
#pragma unroll
    for (int i = 0; i < 4; ++i) {
        float2* prow = (float2*)&sm.e.pre[ey * 4 + i][cx * 8];
#pragma unroll
        for (int j = 0; j < 4; ++j) prow[j] = acc[i][j].f2;
    }
    __syncthreads();

    // epilogue: 8 threads per edge, 32 edges per pass
#pragma unroll
    for (int p = 0; p < 2; ++p) {
        int e = p * 32 + (tid >> 3);
        int l8 = tid & 7;
        int c4 = l8 * 2;   // float4 index of col 8*l8
        int src = s_src[e], tgt = s_tgt[e];
        const float4* np  = (const float4*)(g_NP + (size_t)src * 256);
        const float4* npT = (const float4*)(g_NP + (size_t)tgt * 256);
        float4 sf0 = np[c4],       sf1 = np[c4 + 1];        // src, f
        float4 ss0 = np[16 + c4],  ss1 = np[17 + c4];        // src, s
        float4 tf0 = npT[32 + c4], tf1 = npT[33 + c4];       // tgt, f
        float4 ts0 = npT[48 + c4], ts1 = npT[49 + c4];       // tgt, s
        float4 pf0 = *(const float4*)&sm.e.pre[e][l8 * 8];
        float4 pf1 = *(const float4*)&sm.e.pre[e][l8 * 8 + 4];
        float4 ps0 = *(const float4*)&sm.e.pre[e][64 + l8 * 8];
        float4 ps1 = *(const float4*)&sm.e.pre[e][64 + l8 * 8 + 4];

        float fv[8] = { pf0.x + sf0.x + tf0.x, pf0.y + sf0.y + tf0.y,
                        pf0.z + sf0.z + tf0.z, pf0.w + sf0.w + tf0.w,
                        pf1.x + sf1.x + tf1.x, pf1.y + sf1.y + tf1.y,
                        pf1.z + sf1.z + tf1.z, pf1.w + sf1.w + tf1.w };
        float sv[8] = { ps0.x + ss0.x + ts0.x, ps0.y + ss0.y + ts0.y,
                        ps0.z + ss0.z + ts0.z, ps0.w + ss0.w + ts0.w,
                        ps1.x + ss1.x + ts1.x, ps1.y + ss1.y + ts1.y,
                        ps1.z + ss1.z + ts1.z, ps1.w + ss1.w + ts1.w };
        float h[8];
#pragma unroll
        for (int j = 0; j < 8; ++j)
            h[j] = sigmoidf_(fv[j]) * softplusf_(sv[j]);

        float* dst = g_msg + (size_t)src * 64 + l8 * 8;
        red4(dst,     h[0], h[1], h[2], h[3]);
        red4(dst + 4, h[4], h[5], h[6], h[7]);
    }
}

// ---------------- kernel 3: BN statistics reduction ----------------
__global__ void bn_reduce() {
    __shared__ float sh[2][256];
    int tid = threadIdx.x;
    int f = tid & 63, g = tid >> 6;
    float s = 0.0f, s2 = 0.0f;
    for (int n = blockIdx.x * 4 + g; n < N_NODES; n += gridDim.x * 4) {
        float v = g_msg[(size_t)n * 64 + f];
        s += v; s2 += v * v;
    }
    sh[0][tid] = s; sh[1][tid] = s2;
    __syncthreads();
    if (tid < 64) {
#pragma unroll
        for (int gg = 1; gg < 4; ++gg) { s += sh[0][tid + 64 * gg]; s2 += sh[1][tid + 64 * gg]; }
        atomicAdd(&g_stats[f], (double)s);
        atomicAdd(&g_stats[64 + f], (double)s2);
    }
}

__global__ void bn_stats(const float* __restrict__ gamma, const float* __restrict__ beta) {
    int f = threadIdx.x;
    double invN = 1.0 / (double)N_NODES;
    double mean = g_stats[f] * invN;
    double var = g_stats[64 + f] * invN - mean * mean;
    if (var < 0.0) var = 0.0;
    float sc = (float)(rsqrt(var + 1e-5) * (double)gamma[f]);
    g_scale[f] = sc;
    g_shift[f] = beta[f] - (float)mean * sc;
}

// ---------------- kernel 4: residual + affine BN apply ----------------
__global__ void finalize(const float* __restrict__ node, float* __restrict__ out) {
    int idx = blockIdx.x * blockDim.x + threadIdx.x;     // float4 index, exact cover
    float4 m = ((const float4*)g_msg)[idx];
    float4 x = ((const float4*)node)[idx];
    int f0 = (idx * 4) & 63;
    float4 r;
    r.x = x.x + m.x * g_scale[f0]     + g_shift[f0];
    r.y = x.y + m.y * g_scale[f0 + 1] + g_shift[f0 + 1];
    r.z = x.z + m.z * g_scale[f0 + 2] + g_shift[f0 + 2];
    r.w = x.w + m.w * g_scale[f0 + 3] + g_shift[f0 + 3];
    ((float4*)out)[idx] = r;
}

// ---------------- launch ----------------
extern "C" void kernel_launch(void* const* d_in, const int* in_sizes, int n_in,
                              void* d_out, int out_size) {
    const float* node  = (const float*)d_in[0];
    const void*  ei    = d_in[1];
    const float* ea    = (const float*)d_in[2];
    const float* Wf    = (const float*)d_in[3];
    const float* bf    = (const float*)d_in[4];
    const float* Ws    = (const float*)d_in[5];
    const float* bs    = (const float*)d_in[6];
    const float* gamma = (const float*)d_in[7];
    const float* beta  = (const float*)d_in[8];
    float* out = (float*)d_out;

    void* pmsg = nullptr; void* pstats = nullptr;
    cudaGetSymbolAddress(&pmsg, g_msg);
    cudaGetSymbolAddress(&pstats, g_stats);
    cudaMemsetAsync(pmsg, 0, (size_t)N_NODES * 64 * sizeof(float));
    cudaMemsetAsync(pstats, 0, 128 * sizeof(double));

    detect_dtype<<<1, 256>>>((const unsigned int*)ei);
    node_gemm<<<(N_NODES + 63) / 64, 256>>>(node, Wf, bf, Ws, bs);
    edge_fused<<<N_EDGES / 64, 256>>>(ea, ei, Wf, Ws);
    bn_reduce<<<296, 256>>>();
    bn_stats<<<1, 64>>>(gamma, beta);
    finalize<<<(N_NODES * 64) / 1024, 256>>>(node, out);
}